// round 3
// baseline (speedup 1.0000x reference)
#include <cuda_runtime.h>
#include <math.h>

// ---------------- dims ----------------
#define NFE 212992              // 8*13*32*64
#define NHE 1064960             // 8*65*32*64
#define NOE 4194304             // 8*256*32*64

// ---------------- physics consts ----------------
#define DTs    300.0f
#define KHc    15.0f
#define KVc    0.1f
#define LVc    2.5e6f
#define CPc    1005.0f
#define RGASc  8.314f
#define RDc    287.0f
#define OMEGAc 7.29e-5f
#define EMISc  0.7f
#define SIGMAc 5.67e-8f
#define PIXYc  ((float)(M_PI * 6371000.0 / 33.0))

__constant__ float c_DZ[13]  = {50.f,50.f,50.f,50.f,50.f,75.f,100.f,100.f,100.f,125.f,112.f,75.f,75.f};
__constant__ float c_PRS[13] = {50.f,100.f,150.f,200.f,250.f,300.f,400.f,500.f,600.f,700.f,850.f,925.f,1000.f};

// ---------------- scratch (__device__ globals; no allocation) ----------------
__device__ float g_h[NHE], g_o65[NHE];
__device__ float g_o2[NOE];
__device__ float g_fld[5][NFE];                       // z,q,u,v,t post-BN
__device__ float g_zx[NFE], g_zy[NFE], g_zz[NFE], g_ux[NFE], g_vy[NFE];
__device__ float g_w[NFE], g_rate[NFE];
__device__ float g_sa[NFE], g_sb[NFE];                // RK stage inputs
__device__ float g_ax[NFE], g_ay[NFE], g_az[NFE];     // first derivs field A
__device__ float g_bx[NFE], g_by[NFE], g_bz[NFE];     // first derivs field B
__device__ float g_accu[NFE], g_accv[NFE], g_acct[NFE];
__device__ float g_k4t[NFE], g_dq[NFE], g_dzd[NFE];
__device__ float g_m65[65], g_is65[65], g_m256[256], g_is256[256];
__device__ float g_red[27];
__device__ float g_invpx[32], g_fcor[32];

// red slots: 0..4 field min (z,q,u,v,t); 5..9 field max; 10..14 field sum;
//            15 sarg min; 16 sarg max; 17..21 diff min (z,q,u,v,t); 22..26 diff max

// ---------------- helpers ----------------
__device__ __forceinline__ void atomicMinF(float* a, float v) {
    if (v >= 0.f) atomicMin((int*)a, __float_as_int(v));
    else          atomicMax((unsigned int*)a, __float_as_uint(v));
}
__device__ __forceinline__ void atomicMaxF(float* a, float v) {
    if (v >= 0.f) atomicMax((int*)a, __float_as_int(v));
    else          atomicMin((unsigned int*)a, __float_as_uint(v));
}
__device__ __forceinline__ float avoid_inf1(float t) {
    if (t == 0.f) return 1.f;
    if (fabsf(t) < 1.f) return t > 0.f ? 1.f : -1.f;
    return t;
}

struct Pos { int b, v, h, w, i; };
__device__ __forceinline__ Pos decodeP(int i) {
    Pos p; p.i = i; p.w = i & 63; p.h = (i >> 6) & 31;
    int bv = i >> 11; p.v = bv % 13; p.b = bv / 13;
    return p;
}
__device__ __forceinline__ int pidxN(int m, int n) {   // block-replicate pad index
    return m < 2 ? m : (m < n + 2 ? m - 2 : m - 4);
}
__device__ __forceinline__ float dxf(const float* __restrict__ f, const Pos& p) {
    int base = p.i - p.w;
    float g = (f[base + ((p.w + 62) & 63)] - 8.f * f[base + ((p.w + 63) & 63)]
             + 8.f * f[base + ((p.w + 1) & 63)] - f[base + ((p.w + 2) & 63)]) * (1.f / 12.f);
    return g * g_invpx[p.h];
}
__device__ __forceinline__ float dyf(const float* __restrict__ f, const Pos& p) {
    int base = p.i - (p.h << 6);
    float g = (-f[base + (pidxN(p.h, 32) << 6)] + 8.f * f[base + (pidxN(p.h + 1, 32) << 6)]
             - 8.f * f[base + (pidxN(p.h + 3, 32) << 6)] + f[base + (pidxN(p.h + 4, 32) << 6)]) * (1.f / 12.f);
    return g * (1.f / PIXYc);
}
__device__ __forceinline__ float dzf(const float* __restrict__ f, const Pos& p) {
    int base = p.i - (p.v << 11);
    float g = (-f[base + (pidxN(p.v, 13) << 11)] + 8.f * f[base + (pidxN(p.v + 1, 13) << 11)]
             - 8.f * f[base + (pidxN(p.v + 3, 13) << 11)] + f[base + (pidxN(p.v + 4, 13) << 11)]) * (1.f / 12.f);
    return g / c_DZ[p.v];
}

// block reduction (blockDim == 256) -> atomics to g_red; ssum<0 skips the sum
__device__ __forceinline__ void blockRed(float vmn, float vmx, float vsum,
                                         int smn, int smx, int ssum) {
    __shared__ float sh[24];
    __syncthreads();
    #pragma unroll
    for (int o = 16; o; o >>= 1) {
        vmn  = fminf(vmn, __shfl_xor_sync(0xffffffffu, vmn, o));
        vmx  = fmaxf(vmx, __shfl_xor_sync(0xffffffffu, vmx, o));
        vsum += __shfl_xor_sync(0xffffffffu, vsum, o);
    }
    int lane = threadIdx.x & 31, wid = threadIdx.x >> 5;
    if (lane == 0) { sh[wid] = vmn; sh[8 + wid] = vmx; sh[16 + wid] = vsum; }
    __syncthreads();
    if (threadIdx.x == 0) {
        float a = sh[0], b = sh[8], s = sh[16];
        #pragma unroll
        for (int k = 1; k < 8; k++) { a = fminf(a, sh[k]); b = fmaxf(b, sh[8 + k]); s += sh[16 + k]; }
        atomicMinF(&g_red[smn], a);
        atomicMaxF(&g_red[smx], b);
        if (ssum >= 0) atomicAdd(&g_red[ssum], s);
    }
}

// ---------------- init: lat tables + reduction slots ----------------
__global__ void k_init() {
    int t = threadIdx.x;
    if (t < 32) {
        double lat = (90.0 - (double)(t + 1) * (180.0 / 33.0)) * M_PI / 180.0;
        float px = (float)(2.0 * M_PI * 6371000.0 * cos(lat) / 64.0);
        g_invpx[t] = 1.f / px;
        g_fcor[t]  = 2.0f * OMEGAc * sinf((float)lat);
    }
    if (t < 27) {
        float inf = __int_as_float(0x7f800000);
        float v;
        if (t < 5) v = inf;            // field min
        else if (t < 10) v = -inf;     // field max
        else if (t < 15) v = 0.f;      // field sum
        else if (t == 15) v = inf;     // sarg min
        else if (t == 16) v = -inf;    // sarg max
        else if (t < 22) v = inf;      // diff min
        else v = -inf;                 // diff max
        g_red[t] = v;
    }
}

// ---------------- conv3x3 zero-pad, cross-correlation ----------------
// WHICH==0: src = xin (CI=256) -> g_h ; WHICH==1: src = g_o65 (CI=65) -> g_o2
template <int CI, int CO, int WHICH>
__global__ void __launch_bounds__(256) k_conv(const float* __restrict__ xin,
                                              const float* __restrict__ wt,
                                              const float* __restrict__ bias) {
    __shared__ float xs[16][6][68];
    __shared__ float ws[16][9][16];
    const float* __restrict__ src = (WHICH == 0) ? xin : (const float*)g_o65;
    float* dst = (WHICH == 0) ? g_h : g_o2;

    const int tid   = threadIdx.x;
    const int row_t = tid >> 6;          // 0..3
    const int rest  = tid & 63;
    const int cg    = rest & 3;          // co lane
    const int wg    = rest >> 2;         // 0..15 (4 w each)
    const int y0    = blockIdx.y * 4;
    const int b     = blockIdx.z;
    const int co0   = blockIdx.x * 16;

    float acc[4][4];
    #pragma unroll
    for (int k = 0; k < 4; k++)
        #pragma unroll
        for (int j = 0; j < 4; j++) acc[k][j] = 0.f;

    const int NCH = (CI + 15) / 16;
    for (int cc = 0; cc < NCH; cc++) {
        int c0 = cc * 16;
        __syncthreads();
        for (int l = tid; l < 16 * 6 * 66; l += 256) {
            int ci = l / 396; int rem = l - ci * 396;
            int r = rem / 66; int wp = rem - r * 66;
            int hg = y0 - 1 + r;
            float v = 0.f;
            if (hg >= 0 && hg < 32 && wp >= 1 && wp <= 64 && (c0 + ci) < CI)
                v = src[(((b * CI + c0 + ci) << 5) + hg) * 64 + wp - 1];
            xs[ci][r][wp] = v;
        }
        for (int l = tid; l < 16 * 9 * 16; l += 256) {
            int col = l & 15; int t2 = l >> 4;
            int kk = t2 % 9;  int ci = t2 / 9;
            float v = 0.f;
            if ((co0 + col) < CO && (c0 + ci) < CI)
                v = wt[((co0 + col) * CI + c0 + ci) * 9 + kk];
            ws[ci][kk][col] = v;
        }
        __syncthreads();
        #pragma unroll 2
        for (int ci = 0; ci < 16; ci++) {
            #pragma unroll
            for (int r = 0; r < 3; r++) {
                float4 xq = *reinterpret_cast<const float4*>(&xs[ci][row_t + r][wg * 4]);
                float xv4 = xs[ci][row_t + r][wg * 4 + 4];
                float xv5 = xs[ci][row_t + r][wg * 4 + 5];
                #pragma unroll
                for (int k = 0; k < 4; k++) {
                    float w0 = ws[ci][r * 3 + 0][cg + 4 * k];
                    float w1 = ws[ci][r * 3 + 1][cg + 4 * k];
                    float w2 = ws[ci][r * 3 + 2][cg + 4 * k];
                    acc[k][0] += xq.x * w0 + xq.y * w1 + xq.z * w2;
                    acc[k][1] += xq.y * w0 + xq.z * w1 + xq.w * w2;
                    acc[k][2] += xq.z * w0 + xq.w * w1 + xv4 * w2;
                    acc[k][3] += xq.w * w0 + xv4 * w1 + xv5 * w2;
                }
            }
        }
    }
    #pragma unroll
    for (int k = 0; k < 4; k++) {
        int co = co0 + cg + 4 * k;
        if (co < CO) {
            float bs = bias[co];
            float4 o;
            o.x = acc[k][0] + bs; o.y = acc[k][1] + bs;
            o.z = acc[k][2] + bs; o.w = acc[k][3] + bs;
            *reinterpret_cast<float4*>(&dst[(((b * CO + co) << 5) + (y0 + row_t)) * 64 + wg * 4]) = o;
        }
    }
}

// ---------------- BN stats (block per channel, deterministic) ----------------
template <int C, int WHICH>
__global__ void k_bnstats() {
    const float* src = (WHICH == 0) ? g_h : g_o2;
    int c = blockIdx.x;
    float s = 0.f, s2 = 0.f;
    for (int e = threadIdx.x; e < 16384; e += 256) {
        int b = e >> 11, j = e & 2047;
        float v = src[(((b * C + c) << 11)) + j];
        s += v; s2 += v * v;
    }
    __shared__ float sh[16];
    #pragma unroll
    for (int o = 16; o; o >>= 1) {
        s  += __shfl_xor_sync(0xffffffffu, s, o);
        s2 += __shfl_xor_sync(0xffffffffu, s2, o);
    }
    int lane = threadIdx.x & 31, wid = threadIdx.x >> 5;
    if (lane == 0) { sh[wid] = s; sh[8 + wid] = s2; }
    __syncthreads();
    if (threadIdx.x == 0) {
        float a = sh[0], b2 = sh[8];
        #pragma unroll
        for (int k = 1; k < 8; k++) { a += sh[k]; b2 += sh[8 + k]; }
        float m = a * (1.f / 16384.f);
        float var = b2 * (1.f / 16384.f) - m * m;
        if (WHICH == 0) { g_m65[c] = m;  g_is65[c] = rsqrtf(var + 1e-5f); }
        else            { g_m256[c] = m; g_is256[c] = rsqrtf(var + 1e-5f); }
    }
}

// ---------------- BN apply + split to fields + field min/max/sum ----------------
__global__ void k_bnapply(const float* gz, const float* bz, const float* gq, const float* bq,
                          const float* gu, const float* bu, const float* gv, const float* bv,
                          const float* gt, const float* bt) {
    int i = blockIdx.x * 256 + threadIdx.x;
    int bc = i >> 11;
    int c = bc % 65, b = bc / 65;
    int hw = i & 2047;
    int F = c / 13, v = c % 13;
    const float* ga = F == 0 ? gz : F == 1 ? gq : F == 2 ? gu : F == 3 ? gv : gt;
    const float* be = F == 0 ? bz : F == 1 ? bq : F == 2 ? bu : F == 3 ? bv : bt;
    float val = (g_h[i] - g_m65[c]) * g_is65[c] * ga[v] + be[v];
    g_fld[F][((b * 13 + v) << 11) + hw] = val;
    blockRed(val, val, val, F, 5 + F, 10 + F);
}

// ---------------- base derivatives + sarg reduce ----------------
__global__ void k_basederiv() {
    int i = blockIdx.x * 256 + threadIdx.x;
    Pos p = decodeP(i);
    g_zx[i] = dxf(g_fld[0], p);
    g_zy[i] = dyf(g_fld[0], p);
    g_zz[i] = dzf(g_fld[0], p);
    g_ux[i] = dxf(g_fld[2], p);
    g_vy[i] = dyf(g_fld[3], p);
    float tt = g_fld[4][i];
    float tc = tt - 273.15f;
    float s = 17.67f * tc / avoid_inf1(tc + 243.5f);
    blockRed(s, s, 0.f, 15, 16, -1);
}

// ---------------- w_vel column integral ----------------
__global__ void k_wvel() {
    int j = blockIdx.x * 256 + threadIdx.x;       // 16384 columns
    int b = j >> 11, hw = j & 2047;
    float s = 0.f;
    for (int v = 0; v < 13; v++) {
        int off = ((b * 13 + v) << 11) + hw;
        s += c_DZ[v] * (g_ux[off] + g_vy[off]);
        g_w[off] = -s;
    }
}

// ---------------- saturation + precip rate ----------------
__global__ void k_qs() {
    int i = blockIdx.x * 256 + threadIdx.x;
    float zz = g_zz[i];
    float tt = g_fld[4][i];
    float q  = g_fld[1][i];
    float rho = -1.f / avoid_inf1(zz);
    float pr  = rho * RGASc * tt;
    float tc  = tt - 273.15f;
    float s   = 17.67f * tc / avoid_inf1(tc + 243.5f);
    float smn = g_red[15], smx = g_red[16];
    float sc  = (s - smn) / (smx - smn) * 6.48f - 3.47f;
    float es  = 6.112f * expf(sc) * 100.f;
    float qs  = fmaxf(0.622f * es / avoid_inf1(pr - 0.378f * es), 1e-6f);
    float rh  = q / avoid_inf1(qs);
    g_rate[i] = (rh > 0.8f) ? (q - 0.8f * qs) * (1.f / DTs) : 0.f;
}

// ---------------- RK derivative passes ----------------
__global__ void k_deriv2(int sel) {     // A = u-stage, B = v-stage
    int i = blockIdx.x * 256 + threadIdx.x;
    Pos p = decodeP(i);
    const float* A = sel ? g_sa : g_fld[2];
    const float* B = sel ? g_sb : g_fld[3];
    g_ax[i] = dxf(A, p); g_ay[i] = dyf(A, p); g_az[i] = dzf(A, p);
    g_bx[i] = dxf(B, p); g_by[i] = dyf(B, p); g_bz[i] = dzf(B, p);
}
__global__ void k_deriv1(int sel) {     // 0: t base, 1: t stage (g_sa), 2: q base
    int i = blockIdx.x * 256 + threadIdx.x;
    Pos p = decodeP(i);
    const float* A = sel == 0 ? g_fld[4] : sel == 1 ? g_sa : g_fld[1];
    g_ax[i] = dxf(A, p); g_ay[i] = dyf(A, p); g_az[i] = dzf(A, p);
}

// ---------------- uv RK stage ----------------
__global__ void k_uvstage(int stage) {
    int i = blockIdx.x * 256 + threadIdx.x;
    Pos p = decodeP(i);
    const float* ua = stage == 0 ? g_fld[2] : g_sa;
    const float* va = stage == 0 ? g_fld[3] : g_sb;
    float uai = ua[i], vai = va[i];
    float w = g_w[i];
    float f = g_fcor[p.h];
    float ddxa = dxf(g_ax, p), ddya = dyf(g_ay, p), ddza = dzf(g_az, p);
    float ddxb = dxf(g_bx, p), ddyb = dyf(g_by, p), ddzb = dzf(g_bz, p);
    float ku = -uai * g_ux[i] - vai * g_ay[i] - w * g_az[i] + f * vai - g_zx[i]
             + KHc * (ddxa + ddya) + KVc * ddza;
    float kv = -uai * g_bx[i] - vai * g_vy[i] - w * g_bz[i] - f * uai - g_zy[i]
             + KHc * (ddxb + ddyb) + KVc * ddzb;
    float u0 = g_fld[2][i], v0 = g_fld[3][i];
    if (stage == 0) {
        g_accu[i] = ku; g_accv[i] = kv;
        g_sa[i] = u0 + 0.5f * DTs * ku; g_sb[i] = v0 + 0.5f * DTs * kv;
    } else if (stage == 1) {
        g_accu[i] += 2.f * ku; g_accv[i] += 2.f * kv;
        g_sa[i] = u0 + 0.5f * DTs * ku; g_sb[i] = v0 + 0.5f * DTs * kv;
    } else if (stage == 2) {
        g_accu[i] += 2.f * ku; g_accv[i] += 2.f * kv;
        g_sa[i] = u0 + DTs * ku; g_sb[i] = v0 + DTs * kv;
    } else {
        float du = (g_accu[i] + ku) * (DTs / 6.f);
        float dv = (g_accv[i] + kv) * (DTs / 6.f);
        g_accu[i] = du; g_accv[i] = dv;
        blockRed(du, du, 0.f, 19, 24, -1);
        blockRed(dv, dv, 0.f, 20, 25, -1);
    }
}

// ---------------- t RK stage ----------------
__global__ void k_tstage(int stage) {
    int i = blockIdx.x * 256 + threadIdx.x;
    Pos p = decodeP(i);
    const float* ta = stage == 0 ? g_fld[4] : g_sa;
    float tai = ta[i];
    float w = g_w[i], zz = g_zz[i];
    float u0 = g_fld[2][i], v0 = g_fld[3][i];
    float ddx = dxf(g_ax, p), ddy = dyf(g_ay, p), ddz = dzf(g_az, p);
    float taabs = tai + 273.15f;
    float t2 = taabs * taabs;
    float t5 = t2 * t2 * taabs;
    float rc = -(EMISc * SIGMAc * RDc / (CPc * 100.f)) * t5 / c_PRS[p.v];
    float lh = g_rate[i] * (LVc / CPc);
    float kt = -((LVc + 1.f) / CPc) * zz * w - u0 * g_ax[i] - v0 * g_ay[i] - w * g_az[i]
             + KHc * (ddx + ddy) + KVc * ddz + rc + lh;
    float t0 = g_fld[4][i];
    if (stage == 0) { g_acct[i] = kt;            g_sa[i] = t0 + 0.5f * DTs * kt; }
    else if (stage == 1) { g_acct[i] += 2.f * kt; g_sa[i] = t0 + 0.5f * DTs * kt; }
    else if (stage == 2) { g_acct[i] += 2.f * kt; g_sa[i] = t0 + DTs * kt; }
    else {
        g_k4t[i] = kt;
        float dt_ = (g_acct[i] + kt) * (DTs / 6.f);
        g_acct[i] = dt_;
        blockRed(dt_, dt_, 0.f, 21, 26, -1);
    }
}

// ---------------- q tendency ----------------
__global__ void k_qcomb() {
    int i = blockIdx.x * 256 + threadIdx.x;
    Pos p = decodeP(i);
    float w = g_w[i];
    float u0 = g_fld[2][i], v0 = g_fld[3][i];
    float ddx = dxf(g_ax, p), ddy = dyf(g_ay, p), ddz = dzf(g_az, p);
    float qt = -u0 * g_ax[i] - v0 * g_ay[i] - w * g_az[i]
             + KHc * (ddx + ddy) + KVc * ddz - g_rate[i];
    float dq = qt * DTs;
    g_dq[i] = dq;
    blockRed(dq, dq, 0.f, 18, 23, -1);
}

// ---------------- z tendency column integral ----------------
__global__ void k_zt() {
    int j = blockIdx.x * 256 + threadIdx.x;       // 16384 columns
    int b = j >> 11, hw = j & 2047;
    float s = 0.f;
    float inf = __int_as_float(0x7f800000);
    float mn = inf, mx = -inf;
    for (int v = 0; v < 13; v++) {
        int off = ((b * 13 + v) << 11) + hw;
        s += c_DZ[v] * (-RGASc / c_PRS[v]) * g_k4t[off];
        float d = s * DTs;
        g_dzd[off] = d;
        mn = fminf(mn, d); mx = fmaxf(mx, d);
    }
    blockRed(mn, mx, 0.f, 17, 22, -1);
}

// ---------------- apply scale_diff + coef mix -> g_o65 ----------------
__global__ void k_apply65(const float* __restrict__ coef) {
    int i = blockIdx.x * 256 + threadIdx.x;
    int bc = i >> 11;
    int c = bc % 65, b = bc / 65;
    int hw = i & 2047;
    int F = c / 13, v = c % 13;
    int fi = ((b * 13 + v) << 11) + hw;
    float base = g_fld[F][fi];
    float diff = F == 0 ? g_dzd[fi] : F == 1 ? g_dq[fi] :
                 F == 2 ? g_accu[fi] : F == 3 ? g_accv[fi] : g_acct[fi];
    float mn = g_red[F], mx = g_red[5 + F];
    float me = g_red[10 + F] * (1.f / 212992.f);
    float a = (mn - me) * 0.05f;
    float bb = (mx - me) * 0.05f;
    float dmn = g_red[17 + F], dmx = g_red[22 + F];
    float nv = base + (diff - dmn) / (dmx - dmn) * (bb - a) + a;
    float cf = coef[(c << 11) + hw];
    g_o65[i] = cf * nv + (1.f - cf) * g_h[i];
}

// ---------------- final: BN(o2) + x ----------------
__global__ void k_final(const float* __restrict__ x, const float* __restrict__ gblk,
                        const float* __restrict__ bblk, float* __restrict__ out) {
    int i = blockIdx.x * 256 + threadIdx.x;
    int c = (i >> 11) & 255;
    out[i] = (g_o2[i] - g_m256[c]) * g_is256[c] * gblk[c] + bblk[c] + x[i];
}

// ---------------- launcher ----------------
extern "C" void kernel_launch(void* const* d_in, const int* in_sizes, int n_in,
                              void* d_out, int out_size) {
    const float* x        = (const float*)d_in[0];
    const float* w_norm   = (const float*)d_in[1];
    const float* b_norm   = (const float*)d_in[2];
    const float* w_innorm = (const float*)d_in[3];
    const float* b_innorm = (const float*)d_in[4];
    const float* coef     = (const float*)d_in[5];
    const float* gz = (const float*)d_in[6];  const float* bz = (const float*)d_in[7];
    const float* gq = (const float*)d_in[8];  const float* bq = (const float*)d_in[9];
    const float* gu = (const float*)d_in[10]; const float* bu = (const float*)d_in[11];
    const float* gv = (const float*)d_in[12]; const float* bv = (const float*)d_in[13];
    const float* gt = (const float*)d_in[14]; const float* bt = (const float*)d_in[15];
    const float* gblk = (const float*)d_in[16];
    const float* bblk = (const float*)d_in[17];
    float* out = (float*)d_out;

    const int GF = NFE / 256;      // 832
    const int GH = NHE / 256;      // 4160

    k_init<<<1, 64>>>();
    k_conv<256, 65, 0><<<dim3(5, 8, 8), 256>>>(x, w_norm, b_norm);
    k_bnstats<65, 0><<<65, 256>>>();
    k_bnapply<<<GH, 256>>>(gz, bz, gq, bq, gu, bu, gv, bv, gt, bt);
    k_basederiv<<<GF, 256>>>();
    k_wvel<<<64, 256>>>();
    k_qs<<<GF, 256>>>();
    // uv RK4
    for (int s = 0; s < 4; s++) {
        k_deriv2<<<GF, 256>>>(s == 0 ? 0 : 1);
        k_uvstage<<<GF, 256>>>(s);
    }
    // t RK4
    for (int s = 0; s < 4; s++) {
        k_deriv1<<<GF, 256>>>(s == 0 ? 0 : 1);
        k_tstage<<<GF, 256>>>(s);
    }
    // q
    k_deriv1<<<GF, 256>>>(2);
    k_qcomb<<<GF, 256>>>();
    k_zt<<<64, 256>>>();
    k_apply65<<<GH, 256>>>(coef);
    k_conv<65, 256, 1><<<dim3(16, 8, 8), 256>>>(nullptr, w_innorm, b_innorm);
    k_bnstats<256, 1><<<256, 256>>>();
    k_final<<<NOE / 256, 256>>>(x, gblk, bblk, out);
}